// round 12
// baseline (speedup 1.0000x reference)
#include <cuda_runtime.h>
#include <cuda_fp16.h>

// Problem constants: imgs [8,3,1024,1024] fp32, z [N,2] fp32, out [8,2] fp32
#define NY  1024
#define NX  1024
#define NB  8                 // batches (channel-folded)
#define GBLOCK 256            // gather block: 64 point-slots x 4 lanes
#define GSLOTS 64             // point slots per block
#define CHUNK  1728           // points per block (27 steps of 64), 592*1728 >= 1e6
#define GATHER_BLOCKS 592     // 148 SMs * 4 resident = exactly one wave

// Scratch: duplicated-row fp16 image R[y][x][16] = {P[y][x][0:8], P[y+1][x][0:8]}
// 32 MiB, L2-resident. All 4 bilinear taps of a point = 64B contiguous.
__device__ __align__(128) __half g_R[(size_t)NY * NX * 16];
__device__ float g_partial[GATHER_BLOCKS * 16];

// ---------------------------------------------------------------------------
// Kernel 1: fold  imgs[b*3+c][y][x] --sum_c--> fp16, written twice:
//   R[y][x][0:8]  and  R[y-1][x][8:16]  (frozen: 21.5us, 128MB traffic floor)
// ---------------------------------------------------------------------------
__global__ void __launch_bounds__(128) fold_kernel(const float* __restrict__ imgs) {
    const int y = blockIdx.x >> 3;
    const int x = ((blockIdx.x & 7) << 7) + threadIdx.x;

    float s[NB];
    #pragma unroll
    for (int b = 0; b < NB; b++) {
        s[b] = 0.f;
        #pragma unroll
        for (int c = 0; c < 3; c++)
            s[b] += imgs[((size_t)(b * 3 + c) * NY + y) * NX + x];
    }
    __half2 h[4];
    #pragma unroll
    for (int k = 0; k < 4; k++)
        h[k] = __floats2half2_rn(s[2 * k], s[2 * k + 1]);
    const uint4 v = *reinterpret_cast<const uint4*>(h);

    *reinterpret_cast<uint4*>(g_R + ((size_t)y * NX + x) * 16) = v;
    if (y > 0)
        *reinterpret_cast<uint4*>(g_R + ((size_t)(y - 1) * NX + x) * 16 + 8) = v;
}

// ---------------------------------------------------------------------------
// Weight/address computation for one point (lane view).
//   c0 = s*(col? wxv:w1x), c1 = s*(row? wyv:w1y), s = (q==1||q==2)?+1:-1
// Sentinel z = (-1,-1) -> oob -> both coefficients exactly 0 (safe padding).
// ---------------------------------------------------------------------------
__device__ __forceinline__ void point_setup(
    float2 zz, int row, int col, float s,
    float& c0, float& c1, unsigned& off)
{
    float x0y = zz.x * 1023.0f;
    float x0x = zz.y * 1023.0f;
    bool oob = (x0y < 0.f) | (x0y > 1023.f) | (x0x < 0.f) | (x0x > 1023.f);
    if (oob) { x0y = 0.f; x0x = 0.f; }
    float ygf = floorf(x0y), xgf = floorf(x0x);
    int   yg = min((int)ygf, NY - 2);   // safety clamp (never binds for z in [0,1))
    int   xg = min((int)xgf, NX - 2);
    float fy = ygf - x0y,  fx = xgf - x0x;     // in (-1, 0]
    float valid = oob ? 0.f : 1.f;
    float w1x = (1.f + fx) * valid, wxv = fx * valid;
    float w1y = (1.f + fy) * valid, wyv = fy * valid;
    c0 = s * (col ? wxv : w1x);
    c1 = s * (row ? wyv : w1y);
    off = (unsigned)(((yg << 10) + xg + col) << 5) + (row << 4);   // byte offset
}

__device__ __forceinline__ void accum(
    uint4 raw, float c0, float c1,
    float* __restrict__ a0, float* __restrict__ a1)
{
    const __half2* hp = reinterpret_cast<const __half2*>(&raw);
    #pragma unroll
    for (int k = 0; k < 4; k++) {
        float2 f = __half22float2(hp[k]);
        a0[2*k]   = fmaf(c0, f.x, a0[2*k]);
        a0[2*k+1] = fmaf(c0, f.y, a0[2*k+1]);
        a1[2*k]   = fmaf(c1, f.x, a1[2*k]);
        a1[2*k+1] = fmaf(c1, f.y, a1[2*k+1]);
    }
}

// ---------------------------------------------------------------------------
// Kernel 2: smem-staged gather. Block stages its contiguous 1728-point z chunk
// into shared memory (coalesced; sentinel-padded), so the hot loop's only
// gmem access is the 16B tap load. Warp = 8 points x 4 lanes; unroll 3
// (27 = 3*9 steps, no remainder). Deterministic fixed-order reduction.
// ---------------------------------------------------------------------------
__global__ void __launch_bounds__(GBLOCK, 4) gather_kernel(const float* __restrict__ z, int n) {
    const int t    = threadIdx.x;
    const int q    = t & 3;
    const int row  = q & 1;
    const int col  = q >> 1;
    const float s  = ((q == 1) | (q == 2)) ? 1.f : -1.f;
    const int pl   = t >> 2;                        // point slot 0..63
    const int start = blockIdx.x * CHUNK;

    const float2* __restrict__ z2 = reinterpret_cast<const float2*>(z);
    const __half* __restrict__ R  = g_R;

    __shared__ float2 sz[CHUNK];
    for (int i = t; i < CHUNK; i += GBLOCK) {
        int gi = start + i;
        sz[i] = (gi < n) ? __ldg(&z2[gi]) : make_float2(-1.f, -1.f);
    }
    __syncthreads();

    float a0[NB], a1[NB];
    #pragma unroll
    for (int k = 0; k < NB; k++) { a0[k] = 0.f; a1[k] = 0.f; }

    #pragma unroll 1
    for (int st = 0; st < CHUNK / GSLOTS; st += 3) {
        float2 zz[3];
        #pragma unroll
        for (int k = 0; k < 3; k++)
            zz[k] = sz[pl + (st + k) * GSLOTS];

        float c0[3], c1[3];
        unsigned off[3];
        uint4 raw[3];
        #pragma unroll
        for (int k = 0; k < 3; k++) {
            point_setup(zz[k], row, col, s, c0[k], c1[k], off[k]);
            raw[k] = __ldg(reinterpret_cast<const uint4*>(
                         reinterpret_cast<const char*>(R) + off[k]));
        }
        #pragma unroll
        for (int k = 0; k < 3; k++)
            accum(raw[k], c0[k], c1[k], a0, a1);
    }

    // Safety tail for n > GATHER_BLOCKS*CHUNK (never taken for n = 1e6).
    for (int p = GATHER_BLOCKS * CHUNK + blockIdx.x * GSLOTS + pl;
         p < n; p += GATHER_BLOCKS * GSLOTS) {
        float2 zz = __ldg(&z2[p]);
        float c0, c1; unsigned off;
        point_setup(zz, row, col, s, c0, c1, off);
        uint4 raw = __ldg(reinterpret_cast<const uint4*>(
                        reinterpret_cast<const char*>(R) + off));
        accum(raw, c0, c1, a0, a1);
    }

    // Block reduction: 16 floats per thread -> 16KB smem, fixed order.
    __shared__ float sm[GBLOCK * 16];
    #pragma unroll
    for (int k = 0; k < NB; k++) {
        sm[t * 16 + k * 2    ] = a0[k];
        sm[t * 16 + k * 2 + 1] = a1[k];
    }
    __syncthreads();

    if (t < 16) {             // j = b*2 + o
        float sum = 0.f;
        #pragma unroll 8
        for (int tt = 0; tt < GBLOCK; tt++)
            sum += sm[tt * 16 + t];
        g_partial[blockIdx.x * 16 + t] = sum;
    }
}

// ---------------------------------------------------------------------------
// Kernel 3: deterministic final reduction of GATHER_BLOCKS x 16 partials.
// ---------------------------------------------------------------------------
__global__ void __launch_bounds__(256) reduce_kernel(float* __restrict__ out) {
    __shared__ float red[256];
    const int tid = threadIdx.x;
    const int j = tid & 15, g = tid >> 4;        // 16 outputs x 16 lanes each
    float sum = 0.f;
    for (int i = g; i < GATHER_BLOCKS; i += 16)
        sum += g_partial[i * 16 + j];
    red[tid] = sum;
    __syncthreads();
    if (tid < 16) {
        float s2 = 0.f;
        #pragma unroll
        for (int g2 = 0; g2 < 16; g2++)
            s2 += red[g2 * 16 + tid];
        out[tid] = s2;
    }
}

extern "C" void kernel_launch(void* const* d_in, const int* in_sizes, int n_in,
                              void* d_out, int out_size) {
    const float* imgs = (const float*)d_in[0];   // 8*3*1024*1024 fp32
    const float* z    = (const float*)d_in[1];   // N*2 fp32
    const int n_pts   = in_sizes[1] / 2;

    fold_kernel<<<NY * (NX / 128), 128>>>(imgs);
    gather_kernel<<<GATHER_BLOCKS, GBLOCK>>>(z, n_pts);
    reduce_kernel<<<1, 256>>>((float*)d_out);
}

// round 14
// speedup vs baseline: 1.0467x; 1.0467x over previous
#include <cuda_runtime.h>
#include <cuda_fp16.h>

// Problem constants: imgs [8,3,1024,1024] fp32, z [N,2] fp32, out [8,2] fp32
#define NY  1024
#define NX  1024
#define NB  8                // batches (channel-folded)
#define GBLOCK 256           // gather block: 64 points x 4 lanes
#define GPTS   64            // points per block per step
#define GATHER_BLOCKS 592    // 148 SMs * 4 resident = exactly one wave

// Scratch: duplicated-row fp16 image R[y][x][16] = {P[y][x][0:8], P[y+1][x][0:8]}
// 32 MiB, L2-resident. All 4 bilinear taps of a point = 64B contiguous.
__device__ __align__(128) __half g_R[(size_t)NY * NX * 16];
__device__ float g_partial[GATHER_BLOCKS * 16];
__device__ int   g_ticket;

// ---------------------------------------------------------------------------
// Kernel 1: fold  imgs[b*3+c][y][x] --sum_c--> fp16, written twice:
//   R[y][x][0:8]  and  R[y-1][x][8:16].
// v2: 2 pixels/thread via float2 + __ldcs (evict-first) on the 96MB input
// stream so g_R stays L2-resident for the gather. Also resets the ticket.
// Grid: NY * (NX/256) = 4096 blocks (y = bid>>2, 4 x-tiles of 256px). [R12 bug:
// grid had a stale *2 -> y up to 2047 -> OOB writes. Fixed.]
// ---------------------------------------------------------------------------
__global__ void __launch_bounds__(128) fold_kernel(const float* __restrict__ imgs) {
    if (blockIdx.x == 0 && threadIdx.x == 0) g_ticket = 0;   // graph-replay-safe reset

    const int y = blockIdx.x >> 2;                 // 0..1023
    const int x = ((blockIdx.x & 3) << 8) + threadIdx.x * 2;

    float2 s[NB];
    #pragma unroll
    for (int b = 0; b < NB; b++) {
        s[b] = make_float2(0.f, 0.f);
        #pragma unroll
        for (int c = 0; c < 3; c++) {
            float2 v = __ldcs(reinterpret_cast<const float2*>(
                imgs + ((size_t)(b * 3 + c) * NY + y) * NX + x));
            s[b].x += v.x; s[b].y += v.y;
        }
    }
    __half2 h0[4], h1[4];
    #pragma unroll
    for (int k = 0; k < 4; k++) {
        h0[k] = __floats2half2_rn(s[2 * k].x, s[2 * k + 1].x);   // pixel x
        h1[k] = __floats2half2_rn(s[2 * k].y, s[2 * k + 1].y);   // pixel x+1
    }
    const uint4 v0 = *reinterpret_cast<const uint4*>(h0);
    const uint4 v1 = *reinterpret_cast<const uint4*>(h1);

    __half* base = g_R + ((size_t)y * NX + x) * 16;
    *reinterpret_cast<uint4*>(base)      = v0;
    *reinterpret_cast<uint4*>(base + 16) = v1;
    if (y > 0) {
        __half* up = g_R + ((size_t)(y - 1) * NX + x) * 16;
        *reinterpret_cast<uint4*>(up + 8)      = v0;
        *reinterpret_cast<uint4*>(up + 16 + 8) = v1;
    }
}

// ---------------------------------------------------------------------------
// Weight/address computation for one point (lane view).
//   c0 = s*(col? wxv:w1x), c1 = s*(row? wyv:w1y), s = (q==1||q==2)?+1:-1
// ---------------------------------------------------------------------------
__device__ __forceinline__ void point_setup(
    float2 zz, int row, int col, float s,
    float& c0, float& c1, size_t& addr)
{
    float x0y = zz.x * 1023.0f;
    float x0x = zz.y * 1023.0f;
    bool oob = (x0y < 0.f) | (x0y > 1023.f) | (x0x < 0.f) | (x0x > 1023.f);
    if (oob) { x0y = 0.f; x0x = 0.f; }
    float ygf = floorf(x0y), xgf = floorf(x0x);
    int   yg = min((int)ygf, NY - 2);   // safety clamp (never binds for z in [0,1))
    int   xg = min((int)xgf, NX - 2);
    float fy = ygf - x0y,  fx = xgf - x0x;     // in (-1, 0]
    float valid = oob ? 0.f : 1.f;
    float w1x = (1.f + fx) * valid, wxv = fx * valid;
    float w1y = (1.f + fy) * valid, wyv = fy * valid;
    c0 = s * (col ? wxv : w1x);
    c1 = s * (row ? wyv : w1y);
    addr = ((size_t)yg * NX + (xg + col)) * 16 + row * 8;
}

__device__ __forceinline__ void accum(
    uint4 raw, float c0, float c1,
    float* __restrict__ a0, float* __restrict__ a1)
{
    const __half2* hp = reinterpret_cast<const __half2*>(&raw);
    #pragma unroll
    for (int k = 0; k < 4; k++) {
        float2 f = __half22float2(hp[k]);
        a0[2*k]   = fmaf(c0, f.x, a0[2*k]);
        a0[2*k+1] = fmaf(c0, f.y, a0[2*k+1]);
        a1[2*k]   = fmaf(c1, f.x, a1[2*k]);
        a1[2*k+1] = fmaf(c1, f.y, a1[2*k+1]);
    }
}

// ---------------------------------------------------------------------------
// Kernel 2 (= R7's proven gather + fused final reduce): software-pipelined
// fp16 gather, unroll x4; last-arriving block performs the deterministic
// fixed-order final reduction of all 592x16 partials.
// ---------------------------------------------------------------------------
__global__ void __launch_bounds__(GBLOCK, 4) gather_kernel(
    const float* __restrict__ z, int n, float* __restrict__ out)
{
    const int t    = threadIdx.x;
    const int q    = t & 3;
    const int row  = q & 1;
    const int col  = q >> 1;
    const float s  = ((q == 1) | (q == 2)) ? 1.f : -1.f;
    const int pl   = t >> 2;                        // point slot 0..63
    const int base = blockIdx.x * GPTS + pl;
    const int S    = gridDim.x * GPTS;

    const float2* __restrict__ z2 = reinterpret_cast<const float2*>(z);
    const __half* __restrict__ R  = g_R;

    float a0[NB], a1[NB];
    #pragma unroll
    for (int k = 0; k < NB; k++) { a0[k] = 0.f; a1[k] = 0.f; }

    int p = base;
    for (; p + 3 * S < n; p += 4 * S) {
        float2 zz[4];
        #pragma unroll
        for (int k = 0; k < 4; k++)
            zz[k] = __ldg(&z2[p + k * S]);          // 4 independent z-loads

        float c0[4], c1[4];
        size_t addr[4];
        uint4 raw[4];
        #pragma unroll
        for (int k = 0; k < 4; k++) {
            point_setup(zz[k], row, col, s, c0[k], c1[k], addr[k]);
            raw[k] = __ldg(reinterpret_cast<const uint4*>(R + addr[k]));
        }
        #pragma unroll
        for (int k = 0; k < 4; k++)
            accum(raw[k], c0[k], c1[k], a0, a1);
    }
    for (; p < n; p += S) {
        float2 zz = __ldg(&z2[p]);
        float c0, c1; size_t addr;
        point_setup(zz, row, col, s, c0, c1, addr);
        uint4 raw = __ldg(reinterpret_cast<const uint4*>(R + addr));
        accum(raw, c0, c1, a0, a1);
    }

    // Block reduction: 16 floats per thread -> 16KB smem, fixed order.
    __shared__ float sm[GBLOCK * 16];
    #pragma unroll
    for (int k = 0; k < NB; k++) {
        sm[t * 16 + k * 2    ] = a0[k];
        sm[t * 16 + k * 2 + 1] = a1[k];
    }
    __syncthreads();

    if (t < 16) {             // j = b*2 + o
        float sum = 0.f;
        #pragma unroll 8
        for (int tt = 0; tt < GBLOCK; tt++)
            sum += sm[tt * 16 + t];
        g_partial[blockIdx.x * 16 + t] = sum;
    }

    // Fused final reduce: last-arriving block sums all partials (fixed order).
    __shared__ int s_last;
    __threadfence();
    if (t == 0) s_last = (atomicAdd(&g_ticket, 1) == GATHER_BLOCKS - 1);
    __syncthreads();
    if (s_last) {
        __shared__ float red[256];
        const int j = t & 15, g = t >> 4;            // 16 outputs x 16 lanes
        float sum = 0.f;
        for (int i = g; i < GATHER_BLOCKS; i += 16)
            sum += g_partial[i * 16 + j];
        red[t] = sum;
        __syncthreads();
        if (t < 16) {
            float s2 = 0.f;
            #pragma unroll
            for (int g2 = 0; g2 < 16; g2++)
                s2 += red[g2 * 16 + t];
            out[t] = s2;
        }
    }
}

extern "C" void kernel_launch(void* const* d_in, const int* in_sizes, int n_in,
                              void* d_out, int out_size) {
    const float* imgs = (const float*)d_in[0];   // 8*3*1024*1024 fp32
    const float* z    = (const float*)d_in[1];   // N*2 fp32
    const int n_pts   = in_sizes[1] / 2;

    fold_kernel<<<NY * (NX / 256), 128>>>(imgs);   // 4096 blocks (fixed grid)
    gather_kernel<<<GATHER_BLOCKS, GBLOCK>>>(z, n_pts, (float*)d_out);
}